// round 11
// baseline (speedup 1.0000x reference)
#include <cuda_runtime.h>
#include <cuda_fp16.h>
#include <cstdint>

#define NEG_SLOPE 0.01f

// ---------------------------------------------------------------------------
// Problem constants
// ---------------------------------------------------------------------------
#define NN    65536
#define EE    262144
#define DIN   128
#define DNODE 256
#define DEDGE 272
#define HID   256
#define EA    16

// ---------------------------------------------------------------------------
// Scratch (device globals: allocation is forbidden)
// ---------------------------------------------------------------------------
static __device__ __half g_hnodeH[(size_t)NN * DIN];      // 16 MB
static __device__ __half g_W0t[HID * DEDGE];              // [n=256][k=272]
static __device__ __half g_Wmt[8 * HID * HID];            // [L][n=256][k=256]
static __device__ __half g_Wxt[DIN * DNODE];              // [n=128][k=256]

__device__ __forceinline__ float lrelu(float v) {
    return v >= 0.0f ? v : NEG_SLOPE * v;
}

// ---------------------------------------------------------------------------
// Baseline-PTX helpers
// ---------------------------------------------------------------------------
__device__ __forceinline__ uint32_t smem_u32(const void* p) {
    uint32_t a;
    asm("{ .reg .u64 t; cvta.to.shared.u64 t, %1; cvt.u32.u64 %0, t; }"
        : "=r"(a) : "l"(p));
    return a;
}

__device__ __forceinline__ void ldsm_x4(uint32_t* r, uint32_t addr) {
    asm volatile("ldmatrix.sync.aligned.m8n8.x4.shared.b16 {%0,%1,%2,%3}, [%4];"
                 : "=r"(r[0]), "=r"(r[1]), "=r"(r[2]), "=r"(r[3]) : "r"(addr));
}

__device__ __forceinline__ void mma_f16(float* d, const uint32_t* a,
                                        uint32_t b0, uint32_t b1) {
    asm volatile(
        "mma.sync.aligned.m16n8k16.row.col.f32.f16.f16.f32 "
        "{%0,%1,%2,%3}, {%4,%5,%6,%7}, {%8,%9}, {%0,%1,%2,%3};"
        : "+f"(d[0]), "+f"(d[1]), "+f"(d[2]), "+f"(d[3])
        : "r"(a[0]), "r"(a[1]), "r"(a[2]), "r"(a[3]), "r"(b0), "r"(b1));
}

__device__ __forceinline__ void cp_async16(uint32_t dst, const void* src) {
    asm volatile("cp.async.cg.shared.global [%0], [%1], 16;"
                 :: "r"(dst), "l"(src));
}
#define CP_COMMIT() asm volatile("cp.async.commit_group;")
#define CP_WAIT0()  asm volatile("cp.async.wait_group 0;")

// ---------------------------------------------------------------------------
// Weight prep: fp32 -> fp16, transpose to [n][k]
// ---------------------------------------------------------------------------
__global__ __launch_bounds__(256)
void prep_w0(const float* __restrict__ W0, __half* __restrict__ Wt)
{
    int tid = blockIdx.x * 256 + threadIdx.x;
    if (tid >= DEDGE * HID) return;
    int k = tid >> 8, n = tid & 255;
    Wt[n * DEDGE + k] = __float2half(W0[k * 256 + n]);
}

__global__ __launch_bounds__(256)
void prep_wmid(const float* __restrict__ Wm, __half* __restrict__ Wt)
{
    int tid = blockIdx.x * 256 + threadIdx.x;
    int L = tid >> 16, rem = tid & 0xFFFF;
    int k = rem >> 8, n = rem & 255;
    Wt[(size_t)L * 65536 + n * 256 + k] =
        __float2half(Wm[(size_t)L * 65536 + k * 256 + n]);
}

__global__ __launch_bounds__(256)
void prep_wx(const float* __restrict__ Wx, __half* __restrict__ Wt)
{
    int tid = blockIdx.x * 256 + threadIdx.x;
    if (tid >= DNODE * DIN) return;
    int k = tid >> 7, n = tid & 127;
    Wt[n * DNODE + k] = __float2half(Wx[k * DIN + n]);
}

// ---------------------------------------------------------------------------
// SMEM geometry
// ---------------------------------------------------------------------------
#define STRA   280
#define A_O    0                          // 64*280*2 = 35840
#define W_O    35840
#define W_STG  32768                      // 256 n x 128 B
#define IDX_O  101376                     // rs[64], cs[64]
#define SMEM_TOT 101888
#define NODE_SMEM (35840 + 65536)

// ---------------------------------------------------------------------------
// Node MLP on HMMA (unchanged): hnodeH = fp16(leaky(x @ Wx + bx))
// ---------------------------------------------------------------------------
__global__ __launch_bounds__(256, 2)
void node_hmma(const float* __restrict__ x,
               const __half* __restrict__ Wxt,
               const float* __restrict__ bx,
               __half* __restrict__ hnodeH)
{
    extern __shared__ char smem[];
    const uint32_t sb = smem_u32(smem);
    const int t = threadIdx.x;
    const int wid = t >> 5, lane = t & 31;
    const int wm = wid >> 2, wn = wid & 3;
    const int rowbase = blockIdx.x * 64;
    __half* A = (__half*)(smem + A_O);

#pragma unroll
    for (int i = 0; i < 16; i++) {
        const int j = t + i * 256;
        const int row = j >> 6, k4 = (j & 63) * 4;
        float4 v = *(const float4*)(x + (size_t)(rowbase + row) * DNODE + k4);
        __half2 p0; p0.x = __float2half(v.x); p0.y = __float2half(v.y);
        __half2 p1; p1.x = __float2half(v.z); p1.y = __float2half(v.w);
        *(__half2*)(A + row * STRA + k4) = p0;
        *(__half2*)(A + row * STRA + k4 + 2) = p1;
    }
#pragma unroll
    for (int i = 0; i < 16; i++) {
        const int j = t + i * 256;
        const int ch = j >> 10, r = j & 1023;
        const int n = r >> 3, u = r & 7;
        cp_async16(sb + W_O + ch * 16384 + n * 128 + ((u ^ (n & 7)) << 4),
                   Wxt + (size_t)n * DNODE + ch * 64 + u * 8);
    }
    CP_COMMIT();
    CP_WAIT0();
    __syncthreads();

    const int r16 = lane & 15, khalf = lane >> 4;
    const uint32_t aB0 = sb + A_O +
        (uint32_t)(((wm * 32 + r16) * STRA + khalf * 8) * 2);
    const uint32_t aB1 = aB0 + 16 * STRA * 2;
    const int grp = lane >> 3, wi = lane & 7;
    uint32_t bC[2];
#pragma unroll
    for (int g = 0; g < 2; g++) {
        const int n = wn * 32 + g * 16 + (grp >> 1) * 8 + wi;
        bC[g] = (uint32_t)(n * 128) + ((((uint32_t)(grp & 1)) ^ (n & 7)) << 4);
    }

    float acc[2][4][4];
#pragma unroll
    for (int a = 0; a < 2; a++)
#pragma unroll
        for (int b = 0; b < 4; b++)
#pragma unroll
            for (int c = 0; c < 4; c++) acc[a][b][c] = 0.0f;

#pragma unroll
    for (int kg = 0; kg < 16; kg++) {
        uint32_t af[2][4];
        ldsm_x4(af[0], aB0 + kg * 32);
        ldsm_x4(af[1], aB1 + kg * 32);
        const uint32_t wst = sb + W_O + (kg >> 2) * 16384;
        const uint32_t sbit = (uint32_t)((kg & 3) << 5);
#pragma unroll
        for (int g = 0; g < 2; g++) {
            uint32_t bf[4];
            ldsm_x4(bf, wst + (bC[g] ^ sbit));
#pragma unroll
            for (int mt = 0; mt < 2; mt++) {
                mma_f16(acc[mt][g * 2 + 0], af[mt], bf[0], bf[1]);
                mma_f16(acc[mt][g * 2 + 1], af[mt], bf[2], bf[3]);
            }
        }
    }

#pragma unroll
    for (int mt = 0; mt < 2; mt++) {
        const int r0 = wm * 32 + mt * 16 + (lane >> 2);
#pragma unroll
        for (int nt = 0; nt < 4; nt++) {
            const int col = wn * 32 + nt * 8 + (lane & 3) * 2;
            const float bv0 = __ldg(&bx[col]);
            const float bv1 = __ldg(&bx[col + 1]);
#pragma unroll
            for (int h = 0; h < 2; h++) {
                const int row = r0 + h * 8;
                const float v0 = lrelu(acc[mt][nt][h * 2 + 0] + bv0);
                const float v1 = lrelu(acc[mt][nt][h * 2 + 1] + bv1);
                __half2 p; p.x = __float2half(v0); p.y = __float2half(v1);
                *(__half2*)(hnodeH + (size_t)(rowbase + row) * DIN + col) = p;
            }
        }
    }
}

// ---------------------------------------------------------------------------
// Fused edge pipeline. CTA = 64 edges, 128 threads (4 warps), warp tile
// 64M x 64N (mA=4, nB=8). 2 CTAs/SM. Weight chunks K=64, 2-stage, with
// continuous cross-layer prefetch (parity PO tracks stage).
// ---------------------------------------------------------------------------

// prefetch one weight chunk (nu = 16B units per n-row: 8 full, 2 tail)
template<int NU>
__device__ __forceinline__ void w_prefetch(uint32_t sb, int t,
                                           const __half* __restrict__ W,
                                           int kstride, int k0, uint32_t stage)
{
    const uint32_t st = sb + W_O + stage * W_STG;
#pragma unroll
    for (int i = 0; i < (256 * NU) / 128; i++) {
        const int j = t + i * 128;
        const int n = (NU == 8) ? (j >> 3) : (j >> 1);
        const int u = (NU == 8) ? (j & 7) : (j & 1);
        cp_async16(st + n * 128 + ((u ^ (n & 7)) << 4),
                   W + (size_t)n * kstride + k0 + u * 8);
    }
}

// epilogue: acc -> leaky(+bias) -> fp16 A in place (warp cols wid*64..+64)
__device__ __forceinline__ void epilogue_64(
    float (&acc)[4][8][4], __half* __restrict__ A,
    const float* __restrict__ bias, int wid, int lane)
{
#pragma unroll
    for (int mt = 0; mt < 4; mt++) {
        const int r0 = mt * 16 + (lane >> 2);
#pragma unroll
        for (int nt = 0; nt < 8; nt++) {
            const int col = wid * 64 + nt * 8 + (lane & 3) * 2;
            const float bv0 = __ldg(&bias[col]);
            const float bv1 = __ldg(&bias[col + 1]);
#pragma unroll
            for (int h = 0; h < 2; h++) {
                const int row = r0 + h * 8;
                const float v0 = lrelu(acc[mt][nt][h * 2 + 0] + bv0);
                const float v1 = lrelu(acc[mt][nt][h * 2 + 1] + bv1);
                __half2 p; p.x = __float2half(v0); p.y = __float2half(v1);
                *(__half2*)(A + row * STRA + col) = p;
            }
        }
    }
}

// one k16 compute step (32 MMAs, 4 A-ldsm + 4 B-ldsm)
__device__ __forceinline__ void k16_step(
    float (&acc)[4][8][4], const uint32_t* __restrict__ aB,
    const uint32_t* __restrict__ bC, uint32_t wst, int kg, uint32_t sbit)
{
    uint32_t af[4][4];
#pragma unroll
    for (int mt = 0; mt < 4; mt++) ldsm_x4(af[mt], aB[mt] + kg * 32);
#pragma unroll
    for (int g = 0; g < 4; g++) {
        uint32_t bf[4];
        ldsm_x4(bf, wst + (bC[g] ^ sbit));
#pragma unroll
        for (int mt = 0; mt < 4; mt++) {
            mma_f16(acc[mt][g * 2 + 0], af[mt], bf[0], bf[1]);
            mma_f16(acc[mt][g * 2 + 1], af[mt], bf[2], bf[3]);
        }
    }
}

// Layer 0: KEL=272 (NK16=17, NCH=5), PO=0. Prefetches next layer chunk 0.
__device__ __forceinline__ void gemm_layer0(
    uint32_t sb, __half* __restrict__ A,
    const __half* __restrict__ W, const __half* __restrict__ Wnext,
    const float* __restrict__ bias,
    int t, int wid, int lane,
    const uint32_t* __restrict__ aB, const uint32_t* __restrict__ bC)
{
    float acc[4][8][4];
#pragma unroll
    for (int a = 0; a < 4; a++)
#pragma unroll
        for (int b = 0; b < 8; b++)
#pragma unroll
            for (int c = 0; c < 4; c++) acc[a][b][c] = 0.0f;

#pragma unroll
    for (int c = 0; c < 5; c++) {
        CP_WAIT0();
        __syncthreads();
        if (c < 3)      w_prefetch<8>(sb, t, W, DEDGE, (c + 1) * 64, (c + 1) & 1);
        else if (c == 3) w_prefetch<2>(sb, t, W, DEDGE, 256, 0);       // tail chunk
        else             w_prefetch<8>(sb, t, Wnext, HID, 0, 1);       // next layer c0
        CP_COMMIT();

        const uint32_t wst = sb + W_O + (c & 1) * W_STG;
        const int ks = (c < 4) ? 4 : 1;
#pragma unroll
        for (int s = 0; s < 4; s++) {
            if (s < ks)
                k16_step(acc, aB, bC, wst, c * 4 + s, (uint32_t)(s << 5));
        }
    }
    __syncthreads();
    epilogue_64(acc, A, bias, wid, lane);
}

// Mid layer: KEL=256 (NK16=16, NCH=4), PO=1. Optionally prefetch next c0.
__device__ __forceinline__ void gemm_mid(
    uint32_t sb, __half* __restrict__ A,
    const __half* __restrict__ W, const __half* __restrict__ Wnext,
    const float* __restrict__ bias, bool prefetchNext,
    int t, int wid, int lane,
    const uint32_t* __restrict__ aB, const uint32_t* __restrict__ bC)
{
    float acc[4][8][4];
#pragma unroll
    for (int a = 0; a < 4; a++)
#pragma unroll
        for (int b = 0; b < 8; b++)
#pragma unroll
            for (int c = 0; c < 4; c++) acc[a][b][c] = 0.0f;

#pragma unroll 1
    for (int c = 0; c < 4; c++) {
        CP_WAIT0();
        __syncthreads();
        if (c < 3) {
            w_prefetch<8>(sb, t, W, HID, (c + 1) * 64, (1 + c + 1) & 1);
            CP_COMMIT();
        } else if (prefetchNext) {
            w_prefetch<8>(sb, t, Wnext, HID, 0, 1);   // (PO+NCH)&1 = (1+4)&1 = 1
            CP_COMMIT();
        } else {
            CP_COMMIT();                               // keep group count uniform
        }

        const uint32_t wst = sb + W_O + ((1 + c) & 1) * W_STG;
#pragma unroll
        for (int s = 0; s < 4; s++)
            k16_step(acc, aB, bC, wst, c * 4 + s, (uint32_t)(s << 5));
    }
    __syncthreads();
    epilogue_64(acc, A, bias, wid, lane);
}

__global__ __launch_bounds__(128, 2)
void edge_mlp_fused(const __half* __restrict__ hnodeH,
                    const int* __restrict__ eidx,
                    const float* __restrict__ eattr,
                    const __half* __restrict__ w0,
                    const float* __restrict__ b0,
                    const __half* __restrict__ wm_,
                    const float* __restrict__ bm,
                    const float* __restrict__ Wlast,
                    const float* __restrict__ blast,
                    float* __restrict__ out)
{
    extern __shared__ char smem[];
    const uint32_t sb = smem_u32(smem);
    const int t = threadIdx.x;
    const int wid = t >> 5, lane = t & 31;
    const int rowbase = blockIdx.x * 64;

    int* rs = (int*)(smem + IDX_O);
    int* cs = rs + 64;
    __half* A = (__half*)(smem + A_O);

    // ldmatrix bases (layer-invariant)
    const int r16 = lane & 15, khalf = lane >> 4;
    uint32_t aB[4];
#pragma unroll
    for (int mt = 0; mt < 4; mt++)
        aB[mt] = sb + A_O +
            (uint32_t)(((mt * 16 + r16) * STRA + khalf * 8) * 2);
    const int grp = lane >> 3, wi = lane & 7;
    uint32_t bC[4];
#pragma unroll
    for (int g = 0; g < 4; g++) {
        const int n = wid * 64 + g * 16 + (grp >> 1) * 8 + wi;
        bC[g] = (uint32_t)(n * 128) + ((((uint32_t)(grp & 1)) ^ (n & 7)) << 4);
    }

    // ---- indices, then prefetch layer0 chunk0 (overlaps gather) ----
    if (t < 64) rs[t] = eidx[rowbase + t];
    else        cs[t - 64] = eidx[EE + rowbase + (t - 64)];
    __syncthreads();

    w_prefetch<8>(sb, t, w0, DEDGE, 0, 0);
    CP_COMMIT();

    // ---- gather + concat -> fp16 A0 (64 rows x 272) ----
#pragma unroll
    for (int it = 0; it < 16; it++) {          // hnodeH[row] -> cols 0..127
        const int i = t + it * 128;
        const int row = i >> 5, k4 = (i & 31) * 4;
        uint2 v = *(const uint2*)(hnodeH + (size_t)rs[row] * DIN + k4);
        *(uint2*)(A + row * STRA + k4) = v;
    }
#pragma unroll
    for (int it = 0; it < 16; it++) {          // hnodeH[col] -> cols 128..255
        const int i = t + it * 128;
        const int row = i >> 5, k4 = (i & 31) * 4;
        uint2 v = *(const uint2*)(hnodeH + (size_t)cs[row] * DIN + k4);
        *(uint2*)(A + row * STRA + 128 + k4) = v;
    }
#pragma unroll
    for (int it = 0; it < 4; it++) {           // eattr -> cols 256..271
        const int i = t + it * 128;
        const int row = i >> 3, k2 = (i & 7) * 2;
        float2 v = *(const float2*)(eattr + (size_t)(rowbase + row) * EA + k2);
        __half2 p; p.x = __float2half(v.x); p.y = __float2half(v.y);
        *(__half2*)(A + row * STRA + 256 + k2) = p;
    }
    __syncthreads();

    // ---- 9 GEMM layers (continuous weight-chunk stream) ----
    gemm_layer0(sb, A, w0, wm_, b0, t, wid, lane, aB, bC);
#pragma unroll 1
    for (int L = 0; L < 8; L++)
        gemm_mid(sb, A, wm_ + (size_t)L * 65536, wm_ + (size_t)(L + 1) * 65536,
                 bm + L * 256, L < 7, t, wid, lane, aB, bC);
    __syncthreads();   // A final visible to all warps for head

    // ---- head: logits + log_softmax (each warp -> 16 rows) ----
    for (int r = 0; r < 16; r++) {
        const int row = wid * 16 + r;
        float a0 = 0.f, a1 = 0.f, a2 = 0.f;
#pragma unroll
        for (int k = lane; k < 256; k += 32) {
            const float hv = __half2float(A[row * STRA + k]);
            a0 = fmaf(hv, __ldg(&Wlast[k * 3 + 0]), a0);
            a1 = fmaf(hv, __ldg(&Wlast[k * 3 + 1]), a1);
            a2 = fmaf(hv, __ldg(&Wlast[k * 3 + 2]), a2);
        }
#pragma unroll
        for (int o = 16; o > 0; o >>= 1) {
            a0 += __shfl_down_sync(0xFFFFFFFFu, a0, o);
            a1 += __shfl_down_sync(0xFFFFFFFFu, a1, o);
            a2 += __shfl_down_sync(0xFFFFFFFFu, a2, o);
        }
        if (lane == 0) {
            a0 += __ldg(&blast[0]); a1 += __ldg(&blast[1]); a2 += __ldg(&blast[2]);
            const float m = fmaxf(a0, fmaxf(a1, a2));
            const float s = expf(a0 - m) + expf(a1 - m) + expf(a2 - m);
            const float ls = logf(s) + m;
            float* o = out + (size_t)(rowbase + row) * 3;
            o[0] = a0 - ls; o[1] = a1 - ls; o[2] = a2 - ls;
        }
    }
}

// ---------------------------------------------------------------------------
// Launch
// ---------------------------------------------------------------------------
extern "C" void kernel_launch(void* const* d_in, const int* in_sizes, int n_in,
                              void* d_out, int out_size)
{
    const float* x     = (const float*)d_in[0];
    const int*   eidx  = (const int*)d_in[1];
    const float* eattr = (const float*)d_in[2];
    const float* Wx    = (const float*)d_in[3];
    const float* bx    = (const float*)d_in[4];
    const float* W0    = (const float*)d_in[5];
    const float* b0    = (const float*)d_in[6];
    const float* Wm    = (const float*)d_in[7];
    const float* bm    = (const float*)d_in[8];
    const float* Wl    = (const float*)d_in[9];
    const float* bl    = (const float*)d_in[10];
    float*       out   = (float*)d_out;

    __half *hnodeH, *w0t, *wmt, *wxt;
    cudaGetSymbolAddress((void**)&hnodeH, g_hnodeH);
    cudaGetSymbolAddress((void**)&w0t, g_W0t);
    cudaGetSymbolAddress((void**)&wmt, g_Wmt);
    cudaGetSymbolAddress((void**)&wxt, g_Wxt);

    cudaFuncSetAttribute(edge_mlp_fused,
                         cudaFuncAttributeMaxDynamicSharedMemorySize, SMEM_TOT);
    cudaFuncSetAttribute(node_hmma,
                         cudaFuncAttributeMaxDynamicSharedMemorySize, NODE_SMEM);

    // weight prep
    prep_w0<<<(DEDGE * HID + 255) / 256, 256>>>(W0, w0t);
    prep_wmid<<<(8 * HID * HID) / 256, 256>>>(Wm, wmt);
    prep_wx<<<(DNODE * DIN + 255) / 256, 256>>>(Wx, wxt);

    // node MLP on tensor cores -> fp16 node features
    node_hmma<<<NN / 64, 256, NODE_SMEM>>>(x, wxt, bx, hnodeH);

    // fused edge pipeline (64 edges/CTA, 128 threads, 2 CTAs/SM)
    edge_mlp_fused<<<EE / 64, 128, SMEM_TOT>>>(
        hnodeH, eidx, eattr, w0t, b0, wmt, bm, Wl, bl, out);
}

// round 12
// speedup vs baseline: 1.0124x; 1.0124x over previous
#include <cuda_runtime.h>
#include <cuda_fp16.h>
#include <cstdint>

#define NEG_SLOPE 0.01f

// ---------------------------------------------------------------------------
// Problem constants
// ---------------------------------------------------------------------------
#define NN    65536
#define EE    262144
#define DIN   128
#define DNODE 256
#define DEDGE 272
#define HID   256
#define EA    16

// ---------------------------------------------------------------------------
// Scratch (device globals: allocation is forbidden)
// ---------------------------------------------------------------------------
static __device__ __half g_hnodeH[(size_t)NN * DIN];      // 16 MB
static __device__ __half g_W0t[HID * DEDGE];              // [n=256][k=272]
static __device__ __half g_Wmt[8 * HID * HID];            // [L][n=256][k=256]
static __device__ __half g_Wxt[DIN * DNODE];              // [n=128][k=256]

__device__ __forceinline__ float lrelu(float v) {
    return v >= 0.0f ? v : NEG_SLOPE * v;
}

// ---------------------------------------------------------------------------
// Baseline-PTX helpers
// ---------------------------------------------------------------------------
__device__ __forceinline__ uint32_t smem_u32(const void* p) {
    uint32_t a;
    asm("{ .reg .u64 t; cvta.to.shared.u64 t, %1; cvt.u32.u64 %0, t; }"
        : "=r"(a) : "l"(p));
    return a;
}

__device__ __forceinline__ void ldsm_x4(uint32_t* r, uint32_t addr) {
    asm volatile("ldmatrix.sync.aligned.m8n8.x4.shared.b16 {%0,%1,%2,%3}, [%4];"
                 : "=r"(r[0]), "=r"(r[1]), "=r"(r[2]), "=r"(r[3]) : "r"(addr));
}

__device__ __forceinline__ void mma_f16(float* d, const uint32_t* a,
                                        uint32_t b0, uint32_t b1) {
    asm volatile(
        "mma.sync.aligned.m16n8k16.row.col.f32.f16.f16.f32 "
        "{%0,%1,%2,%3}, {%4,%5,%6,%7}, {%8,%9}, {%0,%1,%2,%3};"
        : "+f"(d[0]), "+f"(d[1]), "+f"(d[2]), "+f"(d[3])
        : "r"(a[0]), "r"(a[1]), "r"(a[2]), "r"(a[3]), "r"(b0), "r"(b1));
}

__device__ __forceinline__ void cp_async16(uint32_t dst, const void* src) {
    asm volatile("cp.async.cg.shared.global [%0], [%1], 16;"
                 :: "r"(dst), "l"(src));
}
#define CP_COMMIT() asm volatile("cp.async.commit_group;")
#define CP_WAIT0()  asm volatile("cp.async.wait_group 0;")
#define BAR_GRP(id) asm volatile("bar.sync %0, 128;" :: "r"(id) : "memory")

// ---------------------------------------------------------------------------
// Weight prep: fp32 -> fp16, transpose to [n][k]
// ---------------------------------------------------------------------------
__global__ __launch_bounds__(256)
void prep_w0(const float* __restrict__ W0, __half* __restrict__ Wt)
{
    int tid = blockIdx.x * 256 + threadIdx.x;
    if (tid >= DEDGE * HID) return;
    int k = tid >> 8, n = tid & 255;
    Wt[n * DEDGE + k] = __float2half(W0[k * 256 + n]);
}

__global__ __launch_bounds__(256)
void prep_wmid(const float* __restrict__ Wm, __half* __restrict__ Wt)
{
    int tid = blockIdx.x * 256 + threadIdx.x;
    int L = tid >> 16, rem = tid & 0xFFFF;
    int k = rem >> 8, n = rem & 255;
    Wt[(size_t)L * 65536 + n * 256 + k] =
        __float2half(Wm[(size_t)L * 65536 + k * 256 + n]);
}

__global__ __launch_bounds__(256)
void prep_wx(const float* __restrict__ Wx, __half* __restrict__ Wt)
{
    int tid = blockIdx.x * 256 + threadIdx.x;
    if (tid >= DNODE * DIN) return;
    int k = tid >> 7, n = tid & 127;
    Wt[n * DNODE + k] = __float2half(Wx[k * DIN + n]);
}

// ---------------------------------------------------------------------------
// SMEM geometry
// ---------------------------------------------------------------------------
#define STRA   280
#define A_O    0                          // 64*280*2 = 35840
#define W_O    35840
#define W_STG  32768                      // 256 n x 128 B
#define IDX_O  101376                     // rs[64], cs[64]
#define SMEM_TOT 101888
#define NODE_SMEM (35840 + 65536)

// ---------------------------------------------------------------------------
// Node MLP on HMMA: hnodeH = fp16(leaky(x @ Wx + bx))
// ---------------------------------------------------------------------------
__global__ __launch_bounds__(256, 2)
void node_hmma(const float* __restrict__ x,
               const __half* __restrict__ Wxt,
               const float* __restrict__ bx,
               __half* __restrict__ hnodeH)
{
    extern __shared__ char smem[];
    const uint32_t sb = smem_u32(smem);
    const int t = threadIdx.x;
    const int wid = t >> 5, lane = t & 31;
    const int wm = wid >> 2, wn = wid & 3;
    const int rowbase = blockIdx.x * 64;
    __half* A = (__half*)(smem + A_O);

#pragma unroll
    for (int i = 0; i < 16; i++) {
        const int j = t + i * 256;
        const int row = j >> 6, k4 = (j & 63) * 4;
        float4 v = *(const float4*)(x + (size_t)(rowbase + row) * DNODE + k4);
        __half2 p0; p0.x = __float2half(v.x); p0.y = __float2half(v.y);
        __half2 p1; p1.x = __float2half(v.z); p1.y = __float2half(v.w);
        *(__half2*)(A + row * STRA + k4) = p0;
        *(__half2*)(A + row * STRA + k4 + 2) = p1;
    }
#pragma unroll
    for (int i = 0; i < 16; i++) {
        const int j = t + i * 256;
        const int ch = j >> 10, r = j & 1023;
        const int n = r >> 3, u = r & 7;
        cp_async16(sb + W_O + ch * 16384 + n * 128 + ((u ^ (n & 7)) << 4),
                   Wxt + (size_t)n * DNODE + ch * 64 + u * 8);
    }
    CP_COMMIT();
    CP_WAIT0();
    __syncthreads();

    const int r16 = lane & 15, khalf = lane >> 4;
    const uint32_t aB0 = sb + A_O +
        (uint32_t)(((wm * 32 + r16) * STRA + khalf * 8) * 2);
    const uint32_t aB1 = aB0 + 16 * STRA * 2;
    const int grp = lane >> 3, wi = lane & 7;
    uint32_t bC[2];
#pragma unroll
    for (int g = 0; g < 2; g++) {
        const int n = wn * 32 + g * 16 + (grp >> 1) * 8 + wi;
        bC[g] = (uint32_t)(n * 128) + ((((uint32_t)(grp & 1)) ^ (n & 7)) << 4);
    }

    float acc[2][4][4];
#pragma unroll
    for (int a = 0; a < 2; a++)
#pragma unroll
        for (int b = 0; b < 4; b++)
#pragma unroll
            for (int c = 0; c < 4; c++) acc[a][b][c] = 0.0f;

#pragma unroll
    for (int kg = 0; kg < 16; kg++) {
        uint32_t af[2][4];
        ldsm_x4(af[0], aB0 + kg * 32);
        ldsm_x4(af[1], aB1 + kg * 32);
        const uint32_t wst = sb + W_O + (kg >> 2) * 16384;
        const uint32_t sbit = (uint32_t)((kg & 3) << 5);
#pragma unroll
        for (int g = 0; g < 2; g++) {
            uint32_t bf[4];
            ldsm_x4(bf, wst + (bC[g] ^ sbit));
#pragma unroll
            for (int mt = 0; mt < 2; mt++) {
                mma_f16(acc[mt][g * 2 + 0], af[mt], bf[0], bf[1]);
                mma_f16(acc[mt][g * 2 + 1], af[mt], bf[2], bf[3]);
            }
        }
    }

#pragma unroll
    for (int mt = 0; mt < 2; mt++) {
        const int r0 = wm * 32 + mt * 16 + (lane >> 2);
#pragma unroll
        for (int nt = 0; nt < 4; nt++) {
            const int col = wn * 32 + nt * 8 + (lane & 3) * 2;
            const float bv0 = __ldg(&bx[col]);
            const float bv1 = __ldg(&bx[col + 1]);
#pragma unroll
            for (int h = 0; h < 2; h++) {
                const int row = r0 + h * 8;
                const float v0 = lrelu(acc[mt][nt][h * 2 + 0] + bv0);
                const float v1 = lrelu(acc[mt][nt][h * 2 + 1] + bv1);
                __half2 p; p.x = __float2half(v0); p.y = __float2half(v1);
                *(__half2*)(hnodeH + (size_t)(rowbase + row) * DIN + col) = p;
            }
        }
    }
}

// ---------------------------------------------------------------------------
// Fused pipeline (R9 shape): CTA = 64 edges, 256 threads, 8 warps (2M x 4N,
// warp tile 32x64), 2 CTAs/SM. Continuous cross-layer weight-chunk stream.
// ---------------------------------------------------------------------------

// prefetch one weight chunk (NU = 16B units per n-row: 8 full, 2 tail)
template<int NU>
__device__ __forceinline__ void w_prefetch(uint32_t sb, int t,
                                           const __half* __restrict__ W,
                                           int kstride, int k0, uint32_t stage)
{
    const uint32_t st = sb + W_O + stage * W_STG;
#pragma unroll
    for (int i = 0; i < NU; i++) {                     // 256*NU/256
        const int j = t + i * 256;
        const int n = (NU == 8) ? (j >> 3) : (j >> 1);
        const int u = (NU == 8) ? (j & 7) : (j & 1);
        cp_async16(st + n * 128 + ((u ^ (n & 7)) << 4),
                   W + (size_t)n * kstride + k0 + u * 8);
    }
}

// one k16 step: 2 A-ldsm + 4 B-ldsm, 16 MMAs
__device__ __forceinline__ void k16_step(
    float (&acc)[2][8][4], uint32_t aB0, uint32_t aB1,
    const uint32_t* __restrict__ bC, uint32_t wst, int kg, uint32_t sbit)
{
    uint32_t af[2][4];
    ldsm_x4(af[0], aB0 + kg * 32);
    ldsm_x4(af[1], aB1 + kg * 32);
#pragma unroll
    for (int g = 0; g < 4; g++) {
        uint32_t bf[4];
        ldsm_x4(bf, wst + (bC[g] ^ sbit));
#pragma unroll
        for (int mt = 0; mt < 2; mt++) {
            mma_f16(acc[mt][g * 2 + 0], af[mt], bf[0], bf[1]);
            mma_f16(acc[mt][g * 2 + 1], af[mt], bf[2], bf[3]);
        }
    }
}

// epilogue: acc -> leaky(+bias) -> fp16 A in place
__device__ __forceinline__ void epilogue_32x64(
    float (&acc)[2][8][4], __half* __restrict__ A,
    const float* __restrict__ bias, int wm, int wn, int lane)
{
#pragma unroll
    for (int mt = 0; mt < 2; mt++) {
        const int r0 = wm * 32 + mt * 16 + (lane >> 2);
#pragma unroll
        for (int nt = 0; nt < 8; nt++) {
            const int col = wn * 64 + nt * 8 + (lane & 3) * 2;
            const float bv0 = __ldg(&bias[col]);
            const float bv1 = __ldg(&bias[col + 1]);
#pragma unroll
            for (int h = 0; h < 2; h++) {
                const int row = r0 + h * 8;
                const float v0 = lrelu(acc[mt][nt][h * 2 + 0] + bv0);
                const float v1 = lrelu(acc[mt][nt][h * 2 + 1] + bv1);
                __half2 p; p.x = __float2half(v0); p.y = __float2half(v1);
                *(__half2*)(A + row * STRA + col) = p;
            }
        }
    }
}

// Layer 0: KEL=272, NK16=17, NCH=5, stages c&1; prefetches next layer chunk0.
__device__ __forceinline__ void gemm_layer0(
    uint32_t sb, __half* __restrict__ A,
    const __half* __restrict__ W, const __half* __restrict__ Wnext,
    const float* __restrict__ bias,
    int t, int lane, int wm, int wn,
    uint32_t aB0, uint32_t aB1, const uint32_t* __restrict__ bC)
{
    float acc[2][8][4];
#pragma unroll
    for (int a = 0; a < 2; a++)
#pragma unroll
        for (int b = 0; b < 8; b++)
#pragma unroll
            for (int c = 0; c < 4; c++) acc[a][b][c] = 0.0f;

#pragma unroll
    for (int c = 0; c < 5; c++) {
        CP_WAIT0();
        __syncthreads();
        if (c < 3)       w_prefetch<8>(sb, t, W, DEDGE, (c + 1) * 64, (c + 1) & 1);
        else if (c == 3) w_prefetch<2>(sb, t, W, DEDGE, 256, 0);   // tail k16
        else             w_prefetch<8>(sb, t, Wnext, HID, 0, 1);   // next layer c0
        CP_COMMIT();

        const uint32_t wst = sb + W_O + (c & 1) * W_STG;
        const int ks = (c < 4) ? 4 : 1;
#pragma unroll
        for (int s = 0; s < 4; s++)
            if (s < ks)
                k16_step(acc, aB0, aB1, bC, wst, c * 4 + s, (uint32_t)(s << 5));
    }
    BAR_GRP(1 + wm);            // wm-group: A rows wm*32..+32 reads done
    epilogue_32x64(acc, A, bias, wm, wn, lane);
    // no CTA barrier: next layer's chunk-0 __syncthreads orders A visibility
}

// Mid layer: KEL=256, NK16=16, NCH=4, stages (1+c)&1.
__device__ __forceinline__ void gemm_mid(
    uint32_t sb, __half* __restrict__ A,
    const __half* __restrict__ W, const __half* __restrict__ Wnext,
    const float* __restrict__ bias, bool prefetchNext,
    int t, int lane, int wm, int wn,
    uint32_t aB0, uint32_t aB1, const uint32_t* __restrict__ bC)
{
    float acc[2][8][4];
#pragma unroll
    for (int a = 0; a < 2; a++)
#pragma unroll
        for (int b = 0; b < 8; b++)
#pragma unroll
            for (int c = 0; c < 4; c++) acc[a][b][c] = 0.0f;

#pragma unroll 1
    for (int c = 0; c < 4; c++) {
        CP_WAIT0();
        __syncthreads();
        if (c < 3)
            w_prefetch<8>(sb, t, W, HID, (c + 1) * 64, c & 1);     // (1+c+1)&1
        else if (prefetchNext)
            w_prefetch<8>(sb, t, Wnext, HID, 0, 1);                // (1+4)&1
        CP_COMMIT();                                               // uniform count

        const uint32_t wst = sb + W_O + ((1 + c) & 1) * W_STG;
#pragma unroll
        for (int s = 0; s < 4; s++)
            k16_step(acc, aB0, aB1, bC, wst, c * 4 + s, (uint32_t)(s << 5));
    }
    BAR_GRP(1 + wm);
    epilogue_32x64(acc, A, bias, wm, wn, lane);
}

__global__ __launch_bounds__(256, 2)
void edge_mlp_fused(const __half* __restrict__ hnodeH,
                    const int* __restrict__ eidx,
                    const float* __restrict__ eattr,
                    const __half* __restrict__ w0,
                    const float* __restrict__ b0,
                    const __half* __restrict__ wm_,
                    const float* __restrict__ bm,
                    const float* __restrict__ Wlast,
                    const float* __restrict__ blast,
                    float* __restrict__ out)
{
    extern __shared__ char smem[];
    const uint32_t sb = smem_u32(smem);
    const int t = threadIdx.x;
    const int wid = t >> 5, lane = t & 31;
    const int wm = wid >> 2, wn = wid & 3;
    const int rowbase = blockIdx.x * 64;

    int* rs = (int*)(smem + IDX_O);
    int* cs = rs + 64;
    __half* A = (__half*)(smem + A_O);

    // layer-invariant ldmatrix bases
    const int r16 = lane & 15, khalf = lane >> 4;
    const uint32_t aB0 = sb + A_O +
        (uint32_t)(((wm * 32 + r16) * STRA + khalf * 8) * 2);
    const uint32_t aB1 = aB0 + 16 * STRA * 2;
    const int grp = lane >> 3, wi = lane & 7;
    uint32_t bC[4];
#pragma unroll
    for (int g = 0; g < 4; g++) {
        const int n = wn * 64 + g * 16 + (grp >> 1) * 8 + wi;
        bC[g] = (uint32_t)(n * 128) + ((((uint32_t)(grp & 1)) ^ (n & 7)) << 4);
    }

    // ---- indices, then layer0 chunk0 prefetch overlapping the gather ----
    if (t < 64) rs[t] = eidx[rowbase + t];
    else if (t < 128) cs[t - 64] = eidx[EE + rowbase + (t - 64)];
    __syncthreads();

    w_prefetch<8>(sb, t, w0, DEDGE, 0, 0);
    CP_COMMIT();

    // ---- gather + concat -> fp16 A0 (64 rows x 272), 16B loads ----
#pragma unroll
    for (int it = 0; it < 4; it++) {          // hnodeH[row] -> cols 0..127
        const int i = t + it * 256;           // 0..1023
        const int row = i >> 4, k8 = (i & 15) * 8;
        uint4 v = *(const uint4*)(hnodeH + (size_t)rs[row] * DIN + k8);
        *(uint4*)(A + row * STRA + k8) = v;
    }
#pragma unroll
    for (int it = 0; it < 4; it++) {          // hnodeH[col] -> cols 128..255
        const int i = t + it * 256;
        const int row = i >> 4, k8 = (i & 15) * 8;
        uint4 v = *(const uint4*)(hnodeH + (size_t)cs[row] * DIN + k8);
        *(uint4*)(A + row * STRA + 128 + k8) = v;
    }
#pragma unroll
    for (int it = 0; it < 2; it++) {          // eattr -> cols 256..271
        const int i = t + it * 256;
        const int row = i >> 3, k2 = (i & 7) * 2;
        float2 v = *(const float2*)(eattr + (size_t)(rowbase + row) * EA + k2);
        __half2 p; p.x = __float2half(v.x); p.y = __float2half(v.y);
        *(__half2*)(A + row * STRA + 256 + k2) = p;
    }
    __syncthreads();

    // ---- 9 GEMM layers (continuous weight-chunk stream) ----
    gemm_layer0(sb, A, w0, wm_, b0, t, lane, wm, wn, aB0, aB1, bC);
#pragma unroll 1
    for (int L = 0; L < 8; L++)
        gemm_mid(sb, A, wm_ + (size_t)L * 65536, wm_ + (size_t)(L + 1) * 65536,
                 bm + L * 256, L < 7, t, lane, wm, wn, aB0, aB1, bC);
    __syncthreads();   // head reads rows across wm-groups

    // ---- head: logits + log_softmax (each warp -> 8 rows) ----
    for (int r = 0; r < 8; r++) {
        const int row = wid * 8 + r;
        float a0 = 0.f, a1 = 0.f, a2 = 0.f;
#pragma unroll
        for (int k = lane; k < 256; k += 32) {
            const float hv = __half2float(A[row * STRA + k]);
            a0 = fmaf(hv, __ldg(&Wlast[k * 3 + 0]), a0);
            a1 = fmaf(hv, __ldg(&Wlast[k * 3 + 1]), a1);
            a2 = fmaf(hv, __ldg(&Wlast[k * 3 + 2]), a2);
        }
#pragma unroll
        for (int o = 16; o > 0; o >>= 1) {
            a0 += __shfl_down_sync(0xFFFFFFFFu, a0, o);
            a1 += __shfl_down_sync(0xFFFFFFFFu, a1, o);
            a2 += __shfl_down_sync(0xFFFFFFFFu, a2, o);
        }
        if (lane == 0) {
            a0 += __ldg(&blast[0]); a1 += __ldg(&blast[1]); a2 += __ldg(&blast[2]);
            const float m = fmaxf(a0, fmaxf(a1, a2));
            const float s = expf(a0 - m) + expf(a1 - m) + expf(a2 - m);
            const float ls = logf(s) + m;
            float* o = out + (size_t)(rowbase + row) * 3;
            o[0] = a0 - ls; o[1] = a1 - ls; o[2] = a2 - ls;
        }
    }
}

// ---------------------------------------------------------------------------
// Launch
// ---------------------------------------------------------------------------
extern "C" void kernel_launch(void* const* d_in, const int* in_sizes, int n_in,
                              void* d_out, int out_size)
{
    const float* x     = (const float*)d_in[0];
    const int*   eidx  = (const int*)d_in[1];
    const float* eattr = (const float*)d_in[2];
    const float* Wx    = (const float*)d_in[3];
    const float* bx    = (const float*)d_in[4];
    const float* W0    = (const float*)d_in[5];
    const float* b0    = (const float*)d_in[6];
    const float* Wm    = (const float*)d_in[7];
    const float* bm    = (const float*)d_in[8];
    const float* Wl    = (const float*)d_in[9];
    const float* bl    = (const float*)d_in[10];
    float*       out   = (float*)d_out;

    __half *hnodeH, *w0t, *wmt, *wxt;
    cudaGetSymbolAddress((void**)&hnodeH, g_hnodeH);
    cudaGetSymbolAddress((void**)&w0t, g_W0t);
    cudaGetSymbolAddress((void**)&wmt, g_Wmt);
    cudaGetSymbolAddress((void**)&wxt, g_Wxt);

    cudaFuncSetAttribute(edge_mlp_fused,
                         cudaFuncAttributeMaxDynamicSharedMemorySize, SMEM_TOT);
    cudaFuncSetAttribute(node_hmma,
                         cudaFuncAttributeMaxDynamicSharedMemorySize, NODE_SMEM);

    // weight prep
    prep_w0<<<(DEDGE * HID + 255) / 256, 256>>>(W0, w0t);
    prep_wmid<<<(8 * HID * HID) / 256, 256>>>(Wm, wmt);
    prep_wx<<<(DNODE * DIN + 255) / 256, 256>>>(Wx, wxt);

    // node MLP on tensor cores -> fp16 node features
    node_hmma<<<NN / 64, 256, NODE_SMEM>>>(x, wxt, bx, hnodeH);

    // fused edge pipeline (64 edges/CTA, 256 threads, 2 CTAs/SM)
    edge_mlp_fused<<<EE / 64, 256, SMEM_TOT>>>(
        hnodeH, eidx, eattr, w0t, b0, wmt, bm, Wl, bl, out);
}

// round 13
// speedup vs baseline: 1.0262x; 1.0136x over previous
#include <cuda_runtime.h>
#include <cuda_fp16.h>
#include <cstdint>

#define NEG_SLOPE 0.01f

// ---------------------------------------------------------------------------
// Problem constants
// ---------------------------------------------------------------------------
#define NN    65536
#define EE    262144
#define DIN   128
#define DNODE 256
#define DEDGE 272
#define HID   256
#define EA    16

// ---------------------------------------------------------------------------
// Scratch (device globals: allocation is forbidden)
// ---------------------------------------------------------------------------
static __device__ __half g_hnodeH[(size_t)NN * DIN];      // 16 MB
static __device__ __half g_W0t[HID * DEDGE];              // [n=256][k=272]
static __device__ __half g_Wmt[8 * HID * HID];            // [L][n=256][k=256]
static __device__ __half g_Wxt[DIN * DNODE];              // [n=128][k=256]

__device__ __forceinline__ float lrelu(float v) {
    return v >= 0.0f ? v : NEG_SLOPE * v;
}

// ---------------------------------------------------------------------------
// Baseline-PTX helpers
// ---------------------------------------------------------------------------
__device__ __forceinline__ uint32_t smem_u32(const void* p) {
    uint32_t a;
    asm("{ .reg .u64 t; cvta.to.shared.u64 t, %1; cvt.u32.u64 %0, t; }"
        : "=r"(a) : "l"(p));
    return a;
}

__device__ __forceinline__ void ldsm_x4(uint32_t* r, uint32_t addr) {
    asm volatile("ldmatrix.sync.aligned.m8n8.x4.shared.b16 {%0,%1,%2,%3}, [%4];"
                 : "=r"(r[0]), "=r"(r[1]), "=r"(r[2]), "=r"(r[3]) : "r"(addr));
}

__device__ __forceinline__ void mma_f16(float* d, const uint32_t* a,
                                        uint32_t b0, uint32_t b1) {
    asm volatile(
        "mma.sync.aligned.m16n8k16.row.col.f32.f16.f16.f32 "
        "{%0,%1,%2,%3}, {%4,%5,%6,%7}, {%8,%9}, {%0,%1,%2,%3};"
        : "+f"(d[0]), "+f"(d[1]), "+f"(d[2]), "+f"(d[3])
        : "r"(a[0]), "r"(a[1]), "r"(a[2]), "r"(a[3]), "r"(b0), "r"(b1));
}

__device__ __forceinline__ void cp_async16(uint32_t dst, const void* src) {
    asm volatile("cp.async.cg.shared.global [%0], [%1], 16;"
                 :: "r"(dst), "l"(src));
}
#define CP_COMMIT() asm volatile("cp.async.commit_group;")
#define CP_WAIT0()  asm volatile("cp.async.wait_group 0;")

// ---------------------------------------------------------------------------
// Weight prep: fp32 -> fp16, transpose to [n][k]
// ---------------------------------------------------------------------------
__global__ __launch_bounds__(256)
void prep_w0(const float* __restrict__ W0, __half* __restrict__ Wt)
{
    int tid = blockIdx.x * 256 + threadIdx.x;
    if (tid >= DEDGE * HID) return;
    int k = tid >> 8, n = tid & 255;
    Wt[n * DEDGE + k] = __float2half(W0[k * 256 + n]);
}

__global__ __launch_bounds__(256)
void prep_wmid(const float* __restrict__ Wm, __half* __restrict__ Wt)
{
    int tid = blockIdx.x * 256 + threadIdx.x;
    int L = tid >> 16, rem = tid & 0xFFFF;
    int k = rem >> 8, n = rem & 255;
    Wt[(size_t)L * 65536 + n * 256 + k] =
        __float2half(Wm[(size_t)L * 65536 + k * 256 + n]);
}

__global__ __launch_bounds__(256)
void prep_wx(const float* __restrict__ Wx, __half* __restrict__ Wt)
{
    int tid = blockIdx.x * 256 + threadIdx.x;
    if (tid >= DNODE * DIN) return;
    int k = tid >> 7, n = tid & 127;
    Wt[n * DNODE + k] = __float2half(Wx[k * DIN + n]);
}

// ---------------------------------------------------------------------------
// SMEM geometry (fused kernel: 128 edges/CTA)
// ---------------------------------------------------------------------------
#define STRA   280
#define A_O    0                          // 128*280*2 = 71680
#define W_O    71680                      // 2 stages x 32768
#define W_STG  32768
#define IDX_O  137216                     // rs[128], cs[128]
#define SMEM_TOT 138240
#define NODE_SMEM (35840 + 65536)

// ---------------------------------------------------------------------------
// Node MLP on HMMA: hnodeH = fp16(leaky(x @ Wx + bx))  (unchanged, 64 rows/CTA)
// ---------------------------------------------------------------------------
__global__ __launch_bounds__(256, 2)
void node_hmma(const float* __restrict__ x,
               const __half* __restrict__ Wxt,
               const float* __restrict__ bx,
               __half* __restrict__ hnodeH)
{
    extern __shared__ char smem[];
    const uint32_t sb = smem_u32(smem);
    const int t = threadIdx.x;
    const int wid = t >> 5, lane = t & 31;
    const int wm = wid >> 2, wn = wid & 3;
    const int rowbase = blockIdx.x * 64;
    __half* A = (__half*)(smem + A_O);

#pragma unroll
    for (int i = 0; i < 16; i++) {
        const int j = t + i * 256;
        const int row = j >> 6, k4 = (j & 63) * 4;
        float4 v = *(const float4*)(x + (size_t)(rowbase + row) * DNODE + k4);
        __half2 p0; p0.x = __float2half(v.x); p0.y = __float2half(v.y);
        __half2 p1; p1.x = __float2half(v.z); p1.y = __float2half(v.w);
        *(__half2*)(A + row * STRA + k4) = p0;
        *(__half2*)(A + row * STRA + k4 + 2) = p1;
    }
#pragma unroll
    for (int i = 0; i < 16; i++) {
        const int j = t + i * 256;
        const int ch = j >> 10, r = j & 1023;
        const int n = r >> 3, u = r & 7;
        cp_async16(sb + 35840 + ch * 16384 + n * 128 + ((u ^ (n & 7)) << 4),
                   Wxt + (size_t)n * DNODE + ch * 64 + u * 8);
    }
    CP_COMMIT();
    CP_WAIT0();
    __syncthreads();

    const int r16 = lane & 15, khalf = lane >> 4;
    const uint32_t aB0 = sb + A_O +
        (uint32_t)(((wm * 32 + r16) * STRA + khalf * 8) * 2);
    const uint32_t aB1 = aB0 + 16 * STRA * 2;
    const int grp = lane >> 3, wi = lane & 7;
    uint32_t bC[2];
#pragma unroll
    for (int g = 0; g < 2; g++) {
        const int n = wn * 32 + g * 16 + (grp >> 1) * 8 + wi;
        bC[g] = (uint32_t)(n * 128) + ((((uint32_t)(grp & 1)) ^ (n & 7)) << 4);
    }

    float acc[2][4][4];
#pragma unroll
    for (int a = 0; a < 2; a++)
#pragma unroll
        for (int b = 0; b < 4; b++)
#pragma unroll
            for (int c = 0; c < 4; c++) acc[a][b][c] = 0.0f;

#pragma unroll
    for (int kg = 0; kg < 16; kg++) {
        uint32_t af[2][4];
        ldsm_x4(af[0], aB0 + kg * 32);
        ldsm_x4(af[1], aB1 + kg * 32);
        const uint32_t wst = sb + 35840 + (kg >> 2) * 16384;
        const uint32_t sbit = (uint32_t)((kg & 3) << 5);
#pragma unroll
        for (int g = 0; g < 2; g++) {
            uint32_t bf[4];
            ldsm_x4(bf, wst + (bC[g] ^ sbit));
#pragma unroll
            for (int mt = 0; mt < 2; mt++) {
                mma_f16(acc[mt][g * 2 + 0], af[mt], bf[0], bf[1]);
                mma_f16(acc[mt][g * 2 + 1], af[mt], bf[2], bf[3]);
            }
        }
    }

#pragma unroll
    for (int mt = 0; mt < 2; mt++) {
        const int r0 = wm * 32 + mt * 16 + (lane >> 2);
#pragma unroll
        for (int nt = 0; nt < 4; nt++) {
            const int col = wn * 32 + nt * 8 + (lane & 3) * 2;
            const float bv0 = __ldg(&bx[col]);
            const float bv1 = __ldg(&bx[col + 1]);
#pragma unroll
            for (int h = 0; h < 2; h++) {
                const int row = r0 + h * 8;
                const float v0 = lrelu(acc[mt][nt][h * 2 + 0] + bv0);
                const float v1 = lrelu(acc[mt][nt][h * 2 + 1] + bv1);
                __half2 p; p.x = __float2half(v0); p.y = __float2half(v1);
                *(__half2*)(hnodeH + (size_t)(rowbase + row) * DIN + col) = p;
            }
        }
    }
}

// ---------------------------------------------------------------------------
// Fused pipeline: CTA = 128 edges, 512 threads, 16 warps (4M x 4N, warp
// tile 32x64), 1 CTA/SM. R9 barrier/prologue structure; only M doubled to
// halve per-SM weight L2 traffic (the measured bottleneck).
// ---------------------------------------------------------------------------

// one k16 step: 2 A-ldsm + 4 B-ldsm, 16 MMAs (identical to R9)
__device__ __forceinline__ void k16_step(
    float (&acc)[2][8][4], uint32_t aB0, uint32_t aB1,
    const uint32_t* __restrict__ bC, uint32_t wst, int kg, uint32_t sbit)
{
    uint32_t af[2][4];
    ldsm_x4(af[0], aB0 + kg * 32);
    ldsm_x4(af[1], aB1 + kg * 32);
#pragma unroll
    for (int g = 0; g < 4; g++) {
        uint32_t bf[4];
        ldsm_x4(bf, wst + (bC[g] ^ sbit));
#pragma unroll
        for (int mt = 0; mt < 2; mt++) {
            mma_f16(acc[mt][g * 2 + 0], af[mt], bf[0], bf[1]);
            mma_f16(acc[mt][g * 2 + 1], af[mt], bf[2], bf[3]);
        }
    }
}

// One GEMM layer: A[128 x KEL] @ W^T -> leaky(+bias) -> A in place.
template<int KEL>
__device__ __forceinline__ void gemm_layer(
    uint32_t sb, __half* __restrict__ A,
    const __half* __restrict__ W, const float* __restrict__ bias,
    int t, int lane, int wm, int wn,
    uint32_t aB0, uint32_t aB1, const uint32_t* __restrict__ bC)
{
    constexpr int NK16 = KEL / 16;            // 17 or 16
    constexpr int NCH  = (NK16 + 3) / 4;      // 5 or 4

    float acc[2][8][4];
#pragma unroll
    for (int a = 0; a < 2; a++)
#pragma unroll
        for (int b = 0; b < 8; b++)
#pragma unroll
            for (int c = 0; c < 4; c++) acc[a][b][c] = 0.0f;

    // prologue: prefetch chunk 0 (full: 2048 16B units over 512 threads)
    {
        const uint32_t st = sb + W_O;
#pragma unroll
        for (int i = 0; i < 4; i++) {
            const int j = t + i * 512;
            const int n = j >> 3, u = j & 7;
            cp_async16(st + n * 128 + ((u ^ (n & 7)) << 4),
                       W + (size_t)n * KEL + u * 8);
        }
        CP_COMMIT();
    }

#pragma unroll
    for (int c = 0; c < NCH; c++) {
        CP_WAIT0();
        __syncthreads();          // chunk c landed; all warps done with c-1 stage

        if (c + 1 < NCH) {        // prefetch chunk c+1 into other stage
            const int k0 = (c + 1) * 64;
            const uint32_t st = sb + W_O + ((c + 1) & 1) * W_STG;
            if (KEL - k0 >= 64) {
#pragma unroll
                for (int i = 0; i < 4; i++) {
                    const int j = t + i * 512;
                    const int n = j >> 3, u = j & 7;
                    cp_async16(st + n * 128 + ((u ^ (n & 7)) << 4),
                               W + (size_t)n * KEL + k0 + u * 8);
                }
            } else {              // tail: 16 k elems = 2 units/row, 512 total
                const int n = t >> 1, u = t & 1;
                cp_async16(st + n * 128 + ((u ^ (n & 7)) << 4),
                           W + (size_t)n * KEL + k0 + u * 8);
            }
        }
        CP_COMMIT();

        // compute chunk c (up to 4 k16 steps)
        const uint32_t wst = sb + W_O + (c & 1) * W_STG;
        const int ks = (NK16 - 4 * c >= 4) ? 4 : (NK16 - 4 * c);
#pragma unroll
        for (int s = 0; s < 4; s++)
            if (s < ks)
                k16_step(acc, aB0, aB1, bC, wst, c * 4 + s, (uint32_t)(s << 5));
    }
    __syncthreads();   // all ldsm reads of A done before epilogue overwrites

    // epilogue: bias + leaky -> fp16 A (in place)
#pragma unroll
    for (int mt = 0; mt < 2; mt++) {
        const int r0 = wm * 32 + mt * 16 + (lane >> 2);
#pragma unroll
        for (int nt = 0; nt < 8; nt++) {
            const int col = wn * 64 + nt * 8 + (lane & 3) * 2;
            const float bv0 = __ldg(&bias[col]);
            const float bv1 = __ldg(&bias[col + 1]);
#pragma unroll
            for (int h = 0; h < 2; h++) {
                const int row = r0 + h * 8;
                const float v0 = lrelu(acc[mt][nt][h * 2 + 0] + bv0);
                const float v1 = lrelu(acc[mt][nt][h * 2 + 1] + bv1);
                __half2 p; p.x = __float2half(v0); p.y = __float2half(v1);
                *(__half2*)(A + row * STRA + col) = p;
            }
        }
    }
    __syncthreads();
}

__global__ __launch_bounds__(512, 1)
void edge_mlp_fused(const __half* __restrict__ hnodeH,
                    const int* __restrict__ eidx,
                    const float* __restrict__ eattr,
                    const __half* __restrict__ w0,
                    const float* __restrict__ b0,
                    const __half* __restrict__ wm_,
                    const float* __restrict__ bm,
                    const float* __restrict__ Wlast,
                    const float* __restrict__ blast,
                    float* __restrict__ out)
{
    extern __shared__ char smem[];
    const uint32_t sb = smem_u32(smem);
    const int t = threadIdx.x;
    const int wid = t >> 5, lane = t & 31;
    const int wm = wid >> 2, wn = wid & 3;     // 4M x 4N warp grid
    const int rowbase = blockIdx.x * 128;

    int* rs = (int*)(smem + IDX_O);
    int* cs = rs + 128;
    __half* A = (__half*)(smem + A_O);

    // layer-invariant ldmatrix bases (identical formulas to R9; wm in 0..3)
    const int r16 = lane & 15, khalf = lane >> 4;
    const uint32_t aB0 = sb + A_O +
        (uint32_t)(((wm * 32 + r16) * STRA + khalf * 8) * 2);
    const uint32_t aB1 = aB0 + 16 * STRA * 2;
    const int grp = lane >> 3, wi = lane & 7;
    uint32_t bC[4];
#pragma unroll
    for (int g = 0; g < 4; g++) {
        const int n = wn * 64 + g * 16 + (grp >> 1) * 8 + wi;
        bC[g] = (uint32_t)(n * 128) + ((((uint32_t)(grp & 1)) ^ (n & 7)) << 4);
    }

    // ---- indices ----
    if (t < 128) rs[t] = eidx[rowbase + t];
    else if (t < 256) cs[t - 128] = eidx[EE + rowbase + (t - 128)];
    __syncthreads();

    // ---- gather + concat -> fp16 A0 (128 rows x 272), 16B loads ----
#pragma unroll
    for (int it = 0; it < 4; it++) {          // hnodeH[row] -> cols 0..127
        const int i = t + it * 512;           // 0..2047
        const int row = i >> 4, k8 = (i & 15) * 8;
        uint4 v = *(const uint4*)(hnodeH + (size_t)rs[row] * DIN + k8);
        *(uint4*)(A + row * STRA + k8) = v;
    }
#pragma unroll
    for (int it = 0; it < 4; it++) {          // hnodeH[col] -> cols 128..255
        const int i = t + it * 512;
        const int row = i >> 4, k8 = (i & 15) * 8;
        uint4 v = *(const uint4*)(hnodeH + (size_t)cs[row] * DIN + k8);
        *(uint4*)(A + row * STRA + 128 + k8) = v;
    }
#pragma unroll
    for (int it = 0; it < 2; it++) {          // eattr -> cols 256..271
        const int i = t + it * 512;           // 0..1023
        const int row = i >> 3, k2 = (i & 7) * 2;
        float2 v = *(const float2*)(eattr + (size_t)(rowbase + row) * EA + k2);
        __half2 p; p.x = __float2half(v.x); p.y = __float2half(v.y);
        *(__half2*)(A + row * STRA + 256 + k2) = p;
    }
    __syncthreads();

    // ---- 9 GEMM layers ----
    gemm_layer<DEDGE>(sb, A, w0, b0, t, lane, wm, wn, aB0, aB1, bC);
#pragma unroll 1
    for (int L = 0; L < 8; L++)
        gemm_layer<HID>(sb, A, wm_ + (size_t)L * 65536, bm + L * 256,
                        t, lane, wm, wn, aB0, aB1, bC);

    // ---- head: logits + log_softmax (each warp -> 8 rows) ----
    for (int r = 0; r < 8; r++) {
        const int row = wid * 8 + r;          // 16 warps x 8 = 128 rows
        float a0 = 0.f, a1 = 0.f, a2 = 0.f;
#pragma unroll
        for (int k = lane; k < 256; k += 32) {
            const float hv = __half2float(A[row * STRA + k]);
            a0 = fmaf(hv, __ldg(&Wlast[k * 3 + 0]), a0);
            a1 = fmaf(hv, __ldg(&Wlast[k * 3 + 1]), a1);
            a2 = fmaf(hv, __ldg(&Wlast[k * 3 + 2]), a2);
        }
#pragma unroll
        for (int o = 16; o > 0; o >>= 1) {
            a0 += __shfl_down_sync(0xFFFFFFFFu, a0, o);
            a1 += __shfl_down_sync(0xFFFFFFFFu, a1, o);
            a2 += __shfl_down_sync(0xFFFFFFFFu, a2, o);
        }
        if (lane == 0) {
            a0 += __ldg(&blast[0]); a1 += __ldg(&blast[1]); a2 += __ldg(&blast[2]);
            const float m = fmaxf(a0, fmaxf(a1, a2));
            const float s = expf(a0 - m) + expf(a1 - m) + expf(a2 - m);
            const float ls = logf(s) + m;
            float* o = out + (size_t)(rowbase + row) * 3;
            o[0] = a0 - ls; o[1] = a1 - ls; o[2] = a2 - ls;
        }
    }
}

// ---------------------------------------------------------------------------
// Launch
// ---------------------------------------------------------------------------
extern "C" void kernel_launch(void* const* d_in, const int* in_sizes, int n_in,
                              void* d_out, int out_size)
{
    const float* x     = (const float*)d_in[0];
    const int*   eidx  = (const int*)d_in[1];
    const float* eattr = (const float*)d_in[2];
    const float* Wx    = (const float*)d_in[3];
    const float* bx    = (const float*)d_in[4];
    const float* W0    = (const float*)d_in[5];
    const float* b0    = (const float*)d_in[6];
    const float* Wm    = (const float*)d_in[7];
    const float* bm    = (const float*)d_in[8];
    const float* Wl    = (const float*)d_in[9];
    const float* bl    = (const float*)d_in[10];
    float*       out   = (float*)d_out;

    __half *hnodeH, *w0t, *wmt, *wxt;
    cudaGetSymbolAddress((void**)&hnodeH, g_hnodeH);
    cudaGetSymbolAddress((void**)&w0t, g_W0t);
    cudaGetSymbolAddress((void**)&wmt, g_Wmt);
    cudaGetSymbolAddress((void**)&wxt, g_Wxt);

    cudaFuncSetAttribute(edge_mlp_fused,
                         cudaFuncAttributeMaxDynamicSharedMemorySize, SMEM_TOT);
    cudaFuncSetAttribute(node_hmma,
                         cudaFuncAttributeMaxDynamicSharedMemorySize, NODE_SMEM);

    // weight prep
    prep_w0<<<(DEDGE * HID + 255) / 256, 256>>>(W0, w0t);
    prep_wmid<<<(8 * HID * HID) / 256, 256>>>(Wm, wmt);
    prep_wx<<<(DNODE * DIN + 255) / 256, 256>>>(Wx, wxt);

    // node MLP on tensor cores -> fp16 node features
    node_hmma<<<NN / 64, 256, NODE_SMEM>>>(x, wxt, bx, hnodeH);

    // fused edge pipeline (128 edges/CTA, 512 threads, 1 CTA/SM)
    edge_mlp_fused<<<EE / 128, 512, SMEM_TOT>>>(
        hnodeH, eidx, eattr, w0t, b0, wmt, bm, Wl, bl, out);
}